// round 1
// baseline (speedup 1.0000x reference)
#include <cuda_runtime.h>
#include <cuda_bf16.h>

// AttentionMax: correlation[b,s] = <q[b], sub[b,s]>, argmax over s, one-hot out [bz, ns, 1]
// bz=4096, ns=256, d=128, fp32. Memory-bound: 512MB stream of feat_sub.

#define NS 256
#define D  128

__global__ __launch_bounds__(256, 4)
void attention_max_kernel(const float* __restrict__ q,
                          const float* __restrict__ sub,
                          float* __restrict__ out)
{
    const int b   = blockIdx.x;
    const int tid = threadIdx.x;          // 0..255, one support row per thread

    __shared__ float4 qs[D / 4];          // 32 float4 = 512 B query row
    __shared__ float  sval[NS];
    __shared__ int    sidx[NS];

    if (tid < D / 4) {
        qs[tid] = reinterpret_cast<const float4*>(q + (size_t)b * D)[tid];
    }
    __syncthreads();

    // Each thread streams its own 512B support row: 32 independent float4 LDGs,
    // fully unrolled -> MLP ~32, DRAM latency hidden.
    const float4* row = reinterpret_cast<const float4*>(
        sub + ((size_t)b * NS + tid) * D);

    float acc = 0.0f;
#pragma unroll
    for (int i = 0; i < D / 4; ++i) {
        float4 v  = row[i];
        float4 qq = qs[i];
        acc = fmaf(v.x, qq.x, acc);
        acc = fmaf(v.y, qq.y, acc);
        acc = fmaf(v.z, qq.z, acc);
        acc = fmaf(v.w, qq.w, acc);
    }

    sval[tid] = acc;
    sidx[tid] = tid;
    __syncthreads();

    // Block argmax, first-occurrence (lowest index) tiebreak like jnp.argmax.
#pragma unroll
    for (int s = NS / 2; s > 0; s >>= 1) {
        if (tid < s) {
            float v2 = sval[tid + s];
            int   i2 = sidx[tid + s];
            float v1 = sval[tid];
            int   i1 = sidx[tid];
            if (v2 > v1 || (v2 == v1 && i2 < i1)) {
                sval[tid] = v2;
                sidx[tid] = i2;
            }
        }
        __syncthreads();
    }

    const int best = sidx[0];
    out[(size_t)b * NS + tid] = (tid == best) ? 1.0f : 0.0f;
}

extern "C" void kernel_launch(void* const* d_in, const int* in_sizes, int n_in,
                              void* d_out, int out_size)
{
    const float* q   = (const float*)d_in[0];   // [4096, 128]
    const float* sub = (const float*)d_in[1];   // [4096, 256, 128]
    float*       out = (float*)d_out;           // [4096, 256, 1]

    const int bz = in_sizes[0] / D;             // 4096

    attention_max_kernel<<<bz, NS>>>(q, sub, out);
}

// round 2
// speedup vs baseline: 1.5669x; 1.5669x over previous
#include <cuda_runtime.h>
#include <cuda_bf16.h>
#include <math_constants.h>

// AttentionMax: correlation[b,s] = <q[b], sub[b,s]>, argmax over s, one-hot out [bz, ns, 1]
// bz=4096, ns=256, d=128, fp32.  Memory-bound: 512MB stream of feat_sub.
//
// R2: warp-cooperative rows. Lane l owns float4 chunk l of each 512B row, so
// each warp LDG.128 is fully coalesced (4 L1 wavefronts vs 32 in R1's
// per-thread-row scheme, which saturated L1tex at 91.5% and capped DRAM at 53%).

#define NS 256
#define D  128

__global__ __launch_bounds__(256, 4)
void attention_max_kernel(const float* __restrict__ q,
                          const float* __restrict__ sub,
                          float* __restrict__ out)
{
    const int b    = blockIdx.x;
    const int tid  = threadIdx.x;
    const int warp = tid >> 5;        // 0..7, each warp owns 32 support rows
    const int lane = tid & 31;

    // Query chunk for this lane (stays in registers; coalesced load).
    const float4 qc = reinterpret_cast<const float4*>(q + (size_t)b * D)[lane];

    // Warp's 32 rows start here; row r, chunk l is base[r*32 + l].
    const float4* base = reinterpret_cast<const float4*>(
        sub + ((size_t)b * NS + warp * 32) * D);

    float bestv = -CUDART_INF_F;
    int   besti = 0;

#pragma unroll
    for (int rr = 0; rr < 32; rr += 8) {
        // Batch 8 independent row loads first -> MLP=8 per warp.
        float4 v[8];
#pragma unroll
        for (int j = 0; j < 8; ++j)
            v[j] = base[(rr + j) * 32 + lane];

#pragma unroll
        for (int j = 0; j < 8; ++j) {
            float p = v[j].x * qc.x;
            p = fmaf(v[j].y, qc.y, p);
            p = fmaf(v[j].z, qc.z, p);
            p = fmaf(v[j].w, qc.w, p);
            // Butterfly sum across the warp: all lanes end with the full dot.
            p += __shfl_xor_sync(0xffffffffu, p, 16);
            p += __shfl_xor_sync(0xffffffffu, p, 8);
            p += __shfl_xor_sync(0xffffffffu, p, 4);
            p += __shfl_xor_sync(0xffffffffu, p, 2);
            p += __shfl_xor_sync(0xffffffffu, p, 1);
            // Strictly-greater + ascending row order = first-occurrence argmax.
            if (p > bestv) { bestv = p; besti = warp * 32 + rr + j; }
        }
    }

    __shared__ float wval[8];
    __shared__ int   widx[8];
    __shared__ int   bsh;

    if (lane == 0) { wval[warp] = bestv; widx[warp] = besti; }
    __syncthreads();

    if (tid == 0) {
        float bv = wval[0];
        int   bi = widx[0];
#pragma unroll
        for (int w = 1; w < 8; ++w)
            if (wval[w] > bv) { bv = wval[w]; bi = widx[w]; }
        bsh = bi;
    }
    __syncthreads();

    out[(size_t)b * NS + tid] = (tid == bsh) ? 1.0f : 0.0f;
}

extern "C" void kernel_launch(void* const* d_in, const int* in_sizes, int n_in,
                              void* d_out, int out_size)
{
    const float* q   = (const float*)d_in[0];   // [4096, 128]
    const float* sub = (const float*)d_in[1];   // [4096, 256, 128]
    float*       out = (float*)d_out;           // [4096, 256, 1]

    const int bz = in_sizes[0] / D;             // 4096

    attention_max_kernel<<<bz, NS>>>(q, sub, out);
}

// round 3
// speedup vs baseline: 1.5923x; 1.0162x over previous
#include <cuda_runtime.h>
#include <cuda_bf16.h>
#include <math_constants.h>

// AttentionMax: correlation[b,s] = <q[b], sub[b,s]>, argmax over s, one-hot out [bz, ns, 1]
// bz=4096, ns=256, d=128, fp32. Memory-bound: 512MB stream of feat_sub.
//
// R3: software-pipelined 4-row double buffer (loads always in flight) +
// multi-row shuffle reduction (6 shfls per 4 rows vs 20) + streaming loads.

#define NS 256
#define D  128

// Reduce 4 per-lane partials (rows base..base+3) to full row sums.
// Result: lane L holds sum of row base + ((L>>3)&3), replicated across 8 lanes.
__device__ __forceinline__ float reduce4(float p0, float p1, float p2, float p3,
                                         int lane)
{
    const unsigned FULL = 0xffffffffu;
    // xor16: keep rows {0,1} on bit16=0 lanes, rows {2,3} on bit16=1 lanes.
    bool hi16 = (lane & 16) != 0;
    float s0 = hi16 ? p0 : p2;                  // value I give away
    float s1 = hi16 ? p1 : p3;
    float r0 = __shfl_xor_sync(FULL, s0, 16);
    float r1 = __shfl_xor_sync(FULL, s1, 16);
    float a0 = (hi16 ? p2 : p0) + r0;
    float a1 = (hi16 ? p3 : p1) + r1;
    // xor8: keep slot0 on bit8=0 lanes, slot1 on bit8=1 lanes.
    bool hi8 = (lane & 8) != 0;
    float s = hi8 ? a0 : a1;
    float r = __shfl_xor_sync(FULL, s, 8);
    float acc = (hi8 ? a1 : a0) + r;
    // remaining lane bits 2,1,0 hold unreduced chunks
    acc += __shfl_xor_sync(FULL, acc, 4);
    acc += __shfl_xor_sync(FULL, acc, 2);
    acc += __shfl_xor_sync(FULL, acc, 1);
    return acc;
}

__device__ __forceinline__ float dot4(float4 v, float4 q)
{
    float p = v.x * q.x;
    p = fmaf(v.y, q.y, p);
    p = fmaf(v.z, q.z, p);
    p = fmaf(v.w, q.w, p);
    return p;
}

__global__ __launch_bounds__(256, 4)
void attention_max_kernel(const float* __restrict__ q,
                          const float* __restrict__ sub,
                          float* __restrict__ out)
{
    const int b    = blockIdx.x;
    const int tid  = threadIdx.x;
    const int warp = tid >> 5;        // 0..7, each warp owns 32 support rows
    const int lane = tid & 31;

    const float4 qc = reinterpret_cast<const float4*>(q + (size_t)b * D)[lane];

    const float4* base = reinterpret_cast<const float4*>(
        sub + ((size_t)b * NS + warp * 32) * D);

    const int myrow = (lane >> 3) & 3;          // which row this lane receives
    float bestv = -CUDART_INF_F;
    int   besti = 0;

    float4 va[4], vb[4];
#pragma unroll
    for (int j = 0; j < 4; ++j)
        va[j] = __ldcs(&base[j * 32 + lane]);

#pragma unroll
    for (int rr = 0; rr < 32; rr += 8) {
        // load next 4 rows while reducing va
#pragma unroll
        for (int j = 0; j < 4; ++j)
            vb[j] = __ldcs(&base[(rr + 4 + j) * 32 + lane]);

        {
            float s = reduce4(dot4(va[0], qc), dot4(va[1], qc),
                              dot4(va[2], qc), dot4(va[3], qc), lane);
            if (s > bestv) { bestv = s; besti = warp * 32 + rr + myrow; }
        }

        if (rr + 8 < 32) {
#pragma unroll
            for (int j = 0; j < 4; ++j)
                va[j] = __ldcs(&base[(rr + 8 + j) * 32 + lane]);
        }

        {
            float s = reduce4(dot4(vb[0], qc), dot4(vb[1], qc),
                              dot4(vb[2], qc), dot4(vb[3], qc), lane);
            if (s > bestv) { bestv = s; besti = warp * 32 + rr + 4 + myrow; }
        }
    }

    // Cross-lane argmax (value max, smaller index wins ties).
    const unsigned FULL = 0xffffffffu;
#pragma unroll
    for (int m = 16; m > 0; m >>= 1) {
        float ov = __shfl_xor_sync(FULL, bestv, m);
        int   oi = __shfl_xor_sync(FULL, besti, m);
        if (ov > bestv || (ov == bestv && oi < besti)) { bestv = ov; besti = oi; }
    }

    __shared__ float wval[8];
    __shared__ int   widx[8];

    if (lane == 0) { wval[warp] = bestv; widx[warp] = besti; }
    __syncthreads();

    // Every thread redundantly reduces the 8 warp results (no second barrier).
    float bv = wval[0];
    int   bi = widx[0];
#pragma unroll
    for (int w = 1; w < 8; ++w)
        if (wval[w] > bv) { bv = wval[w]; bi = widx[w]; }

    out[(size_t)b * NS + tid] = (tid == bi) ? 1.0f : 0.0f;
}

extern "C" void kernel_launch(void* const* d_in, const int* in_sizes, int n_in,
                              void* d_out, int out_size)
{
    const float* q   = (const float*)d_in[0];   // [4096, 128]
    const float* sub = (const float*)d_in[1];   // [4096, 256, 128]
    float*       out = (float*)d_out;           // [4096, 256, 1]

    const int bz = in_sizes[0] / D;             // 4096

    attention_max_kernel<<<bz, NS>>>(q, sub, out);
}